// round 8
// baseline (speedup 1.0000x reference)
#include <cuda_runtime.h>
#include <math.h>
#include <stdint.h>

#define NSEQ 2048
#define DIM  1024
#define HEADS 16
#define QKV6 6144
#define HSLL ((long long)NSEQ * NSEQ)

typedef unsigned short bf16;

// ---------------- device scratch (allocation-free) ----------------
__device__ bf16 g_xh[NSEQ * DIM];
__device__ bf16 g_xl[NSEQ * DIM];
__device__ bf16 g_wqh[QKV6 * DIM];
__device__ bf16 g_wql[QKV6 * DIM];
__device__ bf16 g_woh[DIM * DIM];
__device__ bf16 g_wol[DIM * DIM];
__device__ bf16 g_qh[NSEQ * QKV6];
__device__ bf16 g_ql[NSEQ * QKV6];
__device__ bf16 g_vth[DIM * NSEQ];   // vc transposed: [h*64+d][n]
__device__ bf16 g_vtl[DIM * NSEQ];
__device__ bf16 g_t1h[(size_t)HEADS * NSEQ * NSEQ];
__device__ bf16 g_t1l[(size_t)HEADS * NSEQ * NSEQ];
__device__ bf16 g_sgh[(size_t)HEADS * NSEQ * NSEQ];
__device__ bf16 g_sgl[(size_t)HEADS * NSEQ * NSEQ];
__device__ float g_sc[(size_t)HEADS * NSEQ * NSEQ];
__device__ float g_su[(size_t)HEADS * NSEQ * NSEQ];
__device__ bf16 g_ah[(size_t)HEADS * NSEQ * NSEQ];
__device__ bf16 g_al[(size_t)HEADS * NSEQ * NSEQ];
__device__ bf16 g_oh[NSEQ * DIM];
__device__ bf16 g_ol[NSEQ * DIM];

// ---------------- helpers ----------------
__device__ __forceinline__ bf16 f2bf(float f) {
    bf16 h;
    asm("cvt.rn.bf16.f32 %0, %1;" : "=h"(h) : "f"(f));
    return h;
}
__device__ __forceinline__ float bf2f(bf16 h) {
    return __uint_as_float(((unsigned int)h) << 16);
}

__device__ __forceinline__ uint32_t smem_u32(const void* p) {
    uint32_t a;
    asm("{ .reg .u64 t; cvta.to.shared.u64 t, %1; cvt.u32.u64 %0, t; }" : "=r"(a) : "l"(p));
    return a;
}

__device__ __forceinline__ void cpa16(uint32_t saddr, const void* g) {
    asm volatile("cp.async.ca.shared.global [%0], [%1], 16;" :: "r"(saddr), "l"(g));
}
#define CP_COMMIT() asm volatile("cp.async.commit_group;" ::: "memory")
#define CP_WAIT0() asm volatile("cp.async.wait_group 0;" ::: "memory")
#define CP_WAIT1() asm volatile("cp.async.wait_group 1;" ::: "memory")

__device__ __forceinline__ void ldmA(uint32_t* r, uint32_t addr) {
    asm volatile("ldmatrix.sync.aligned.m8n8.x4.shared.b16 {%0,%1,%2,%3}, [%4];"
        : "=r"(r[0]), "=r"(r[1]), "=r"(r[2]), "=r"(r[3]) : "r"(addr));
}
__device__ __forceinline__ void ldmB(uint32_t* r, uint32_t addr) {
    asm volatile("ldmatrix.sync.aligned.m8n8.x2.shared.b16 {%0,%1}, [%2];"
        : "=r"(r[0]), "=r"(r[1]) : "r"(addr));
}

__device__ __forceinline__ void mma16816(float* d, const uint32_t* a, const uint32_t* b) {
    asm volatile(
        "mma.sync.aligned.m16n8k16.row.col.f32.bf16.bf16.f32 "
        "{%0,%1,%2,%3}, {%4,%5,%6,%7}, {%8,%9}, {%0,%1,%2,%3};"
        : "+f"(d[0]), "+f"(d[1]), "+f"(d[2]), "+f"(d[3])
        : "r"(a[0]), "r"(a[1]), "r"(a[2]), "r"(a[3]), "r"(b[0]), "r"(b[1]));
}

// SW64 swizzle: 64-byte rows (BK=32 bf16), atom = 8 rows x 64B
__device__ __forceinline__ uint32_t sw64(uint32_t off) {
    return off ^ ((off >> 3) & 0x30);
}

// ---------------- warp-MMA GEMM engine (bf16x3 split, cp.async 3-stage, BK=32) ----------------
// C[i0+m][n0+n] = sum_k A[m][k]*B[n][k]
// epi: 0 fp32; 1 qkv-scale + split; 2 mask j<=i + split; 3 sigmoid strict-upper + split; 4 split.
// skipm: 1 skip n0>i0; 2 skip n0<i0. trik: 1 -> k in [n0, i0+128); 2 -> k in [0, i0+128).
template<int BN, int WMC>
__global__ void __launch_bounds__(256, 2) mma_gemm(
    const bf16* __restrict__ Ah, const bf16* __restrict__ Al, int lda, long long sA,
    const bf16* __restrict__ Bh, const bf16* __restrict__ Bl, int ldb, long long sB,
    float* Cf, bf16* Ch, bf16* Cl, int ldc, long long sC,
    int K, int epi, int skipm, int trik)
{
    constexpr int WNC = 8 / WMC;
    constexpr int WM = 128 / WMC;
    constexpr int WN = BN / WNC;
    constexpr int MF = WM / 16;
    constexpr int NF = WN / 8;
    // stage layout (SW64 rows of 64B): A hi 8KB, A lo 8KB, B hi BN*64, B lo BN*64
    constexpr int S_AH = 0;
    constexpr int S_AL = 8192;
    constexpr int S_BH = 16384;
    constexpr int S_BL = 16384 + BN * 64;
    constexpr int STG = 16384 + BN * 128;

    int i0 = blockIdx.y * 128;
    int n0 = blockIdx.x * BN;
    if (skipm == 1 && n0 > i0) return;
    if (skipm == 2 && n0 < i0) return;
    int z = blockIdx.z;
    Ah += (long long)z * sA;
    Al += (long long)z * sA;
    Bh += (long long)z * sB;
    Bl += (long long)z * sB;
    if (Cf) Cf += (long long)z * sC;
    if (Ch) {
        Ch += (long long)z * sC;
        Cl += (long long)z * sC;
    }

    int kbeg = 0;
    int kend = K;
    if (trik == 1) {
        kbeg = n0;
        kend = i0 + 128;
        if (kend > K) kend = K;
    } else if (trik == 2) {
        kend = i0 + 128;
        if (kend > K) kend = K;
    }
    int nch = (kend - kbeg + 31) >> 5;

    extern __shared__ __align__(1024) char smem[];
    uint32_t sb = smem_u32(smem);
    int tid = threadIdx.x;
    int wid = tid >> 5;
    int lane = tid & 31;
    int wm = wid % WMC;
    int wn = wid / WMC;

    auto stage_chunk = [&](int buf, int kt) {
        uint32_t base = sb + buf * STG;
        for (int u = tid; u < 512; u += 256) {
            int r = u >> 2;
            int kb = u & 3;
            long long go = (long long)(i0 + r) * lda + kt + kb * 8;
            uint32_t sw = sw64(((uint32_t)r << 6) | ((uint32_t)kb << 4));
            cpa16(base + S_AH + sw, Ah + go);
            cpa16(base + S_AL + sw, Al + go);
        }
        for (int u = tid; u < BN * 4; u += 256) {
            int r = u >> 2;
            int kb = u & 3;
            long long go = (long long)(n0 + r) * ldb + kt + kb * 8;
            uint32_t sw = sw64(((uint32_t)r << 6) | ((uint32_t)kb << 4));
            cpa16(base + S_BH + sw, Bh + go);
            cpa16(base + S_BL + sw, Bl + go);
        }
    };

    float acc[MF][NF][4];
    #pragma unroll
    for (int a = 0; a < MF; a++)
        #pragma unroll
        for (int b = 0; b < NF; b++)
            #pragma unroll
            for (int c = 0; c < 4; c++)
                acc[a][b][c] = 0.f;

    stage_chunk(0, kbeg);
    CP_COMMIT();
    if (nch > 1) {
        stage_chunk(1, kbeg + 32);
        CP_COMMIT();
    }

    int buf = 0;
    for (int t = 0; t < nch; t++) {
        if (t + 1 < nch) {
            CP_WAIT1();
        } else {
            CP_WAIT0();
        }
        __syncthreads();
        // prefetch t+2 into buffer (t+2)%3 — safe: all warps finished reading it (chunk t-1)
        if (t + 2 < nch) {
            int b2 = buf + 2;
            if (b2 >= 3) b2 -= 3;
            stage_chunk(b2, kbeg + (t + 2) * 32);
            CP_COMMIT();
        }

        uint32_t cbase = sb + buf * STG;
        #pragma unroll
        for (int ks = 0; ks < 2; ks++) {
            int g = lane >> 3;
            int rowin = lane & 7;
            int kbA = ks * 32 + (g >> 1) * 16;
            uint32_t ahf[MF][4], alf[MF][4];
            #pragma unroll
            for (int mf = 0; mf < MF; mf++) {
                int r = wm * WM + mf * 16 + (g & 1) * 8 + rowin;
                uint32_t sw = sw64(((uint32_t)r << 6) + (uint32_t)kbA);
                ldmA(ahf[mf], cbase + S_AH + sw);
                ldmA(alf[mf], cbase + S_AL + sw);
            }
            int kbB = ks * 32 + ((lane >> 3) & 1) * 16;
            uint32_t bhf[NF][2], blf[NF][2];
            #pragma unroll
            for (int nf = 0; nf < NF; nf++) {
                int r = wn * WN + nf * 8 + rowin;
                uint32_t sw = sw64(((uint32_t)r << 6) + (uint32_t)kbB);
                ldmB(bhf[nf], cbase + S_BH + sw);
                ldmB(blf[nf], cbase + S_BL + sw);
            }
            #pragma unroll
            for (int mf = 0; mf < MF; mf++) {
                #pragma unroll
                for (int nf = 0; nf < NF; nf++) {
                    mma16816(acc[mf][nf], ahf[mf], bhf[nf]);
                    mma16816(acc[mf][nf], ahf[mf], blf[nf]);
                    mma16816(acc[mf][nf], alf[mf], bhf[nf]);
                }
            }
        }
        buf++;
        if (buf == 3) buf = 0;
    }

    // epilogue from register fragments (vectorized 2-column stores)
    int crow = lane >> 2;
    int ccol = (lane & 3) * 2;
    #pragma unroll
    for (int mf = 0; mf < MF; mf++) {
        #pragma unroll
        for (int nf = 0; nf < NF; nf++) {
            #pragma unroll
            for (int c2 = 0; c2 < 2; c2++) {
                int gi = i0 + wm * WM + mf * 16 + crow + c2 * 8;
                int gj = n0 + wn * WN + nf * 8 + ccol;
                float v0 = acc[mf][nf][c2 * 2];
                float v1 = acc[mf][nf][c2 * 2 + 1];
                long long idx = (long long)gi * ldc + gj;
                if (epi == 0) {
                    float2 f2;
                    f2.x = v0;
                    f2.y = v1;
                    *(float2*)(Cf + idx) = f2;
                } else {
                    if (epi == 1) {
                        int c0 = gj >> 10;
                        int c1 = (gj + 1) >> 10;
                        if (c0 == 0 || c0 == 3) v0 *= 0.125f;
                        if (c1 == 0 || c1 == 3) v1 *= 0.125f;
                    } else if (epi == 2) {
                        v0 = (gj <= gi) ? v0 : 0.f;
                        v1 = (gj + 1 <= gi) ? v1 : 0.f;
                    } else if (epi == 3) {
                        v0 = (gj > gi) ? (1.f / (1.f + expf(-v0))) : 0.f;
                        v1 = (gj + 1 > gi) ? (1.f / (1.f + expf(-v1))) : 0.f;
                    }
                    bf16 h0 = f2bf(v0);
                    bf16 h1 = f2bf(v1);
                    uint32_t hp = (uint32_t)h0 | ((uint32_t)h1 << 16);
                    uint32_t lp = (uint32_t)f2bf(v0 - bf2f(h0)) | ((uint32_t)f2bf(v1 - bf2f(h1)) << 16);
                    *(uint32_t*)(Ch + idx) = hp;
                    *(uint32_t*)(Cl + idx) = lp;
                }
            }
        }
    }
}

// ---------------- split fp32 -> (hi, lo) bf16 ----------------
__global__ void split_kernel(const float* __restrict__ s, bf16* __restrict__ h,
                             bf16* __restrict__ l, int n4)
{
    int i = blockIdx.x * 256 + threadIdx.x;
    if (i < n4) {
        float4 v = ((const float4*)s)[i];
        float vv[4];
        vv[0] = v.x; vv[1] = v.y; vv[2] = v.z; vv[3] = v.w;
        for (int k = 0; k < 4; k++) {
            bf16 hh = f2bf(vv[k]);
            h[i * 4 + k] = hh;
            l[i * 4 + k] = f2bf(vv[k] - bf2f(hh));
        }
    }
}

// ---------------- transpose vc: [n][5120 + c] -> [c][n] ----------------
__global__ void transpose_vc(const bf16* __restrict__ qh, const bf16* __restrict__ ql,
                             bf16* __restrict__ vth, bf16* __restrict__ vtl)
{
    __shared__ bf16 th[32][33];
    __shared__ bf16 tl[32][33];
    int c0 = blockIdx.x * 32;
    int n0 = blockIdx.y * 32;
    int tx = threadIdx.x;
    int ty = threadIdx.y;
    for (int r = ty; r < 32; r += 8) {
        th[r][tx] = qh[(long long)(n0 + r) * QKV6 + 5120 + c0 + tx];
        tl[r][tx] = ql[(long long)(n0 + r) * QKV6 + 5120 + c0 + tx];
    }
    __syncthreads();
    for (int r = ty; r < 32; r += 8) {
        vth[(long long)(c0 + r) * NSEQ + n0 + tx] = th[tx][r];
        vtl[(long long)(c0 + r) * NSEQ + n0 + tx] = tl[tx][r];
    }
}

// ---------------- softmax(Sc - silu(Su)) over j<=i -> attn bf16 pair ----------------
__global__ void softmax_kernel(const float* __restrict__ sc, const float* __restrict__ su,
                               bf16* __restrict__ ah, bf16* __restrict__ al, int n)
{
    int i = blockIdx.x;
    int hh = blockIdx.y;
    long long base = ((long long)hh * n + i) * (long long)n;
    const float* scr = sc + base;
    const float* sur = su + base;
    bf16* ahr = ah + base;
    bf16* alr = al + base;

    int tid = threadIdx.x;
    const int NT = 256;
    float vals[8];
    int cnt = 0;
    float lmax = -INFINITY;
    for (int j = tid; j <= i; j += NT) {
        float u = sur[j];
        float sg = 1.f / (1.f + expf(-u));
        float s = scr[j] - u * sg;
        vals[cnt] = s;
        cnt++;
        lmax = fmaxf(lmax, s);
    }

    __shared__ float red[33];
    for (int o = 16; o > 0; o >>= 1) lmax = fmaxf(lmax, __shfl_xor_sync(0xffffffffu, lmax, o));
    if ((tid & 31) == 0) red[tid >> 5] = lmax;
    __syncthreads();
    if (tid == 0) {
        float m0 = red[0];
        for (int w = 1; w < NT / 32; w++) m0 = fmaxf(m0, red[w]);
        red[32] = m0;
    }
    __syncthreads();
    float m = red[32];
    __syncthreads();

    float lsum = 0.f;
    for (int c = 0; c < cnt; c++) {
        float e = expf(vals[c] - m);
        vals[c] = e;
        lsum += e;
    }
    for (int o = 16; o > 0; o >>= 1) lsum += __shfl_xor_sync(0xffffffffu, lsum, o);
    if ((tid & 31) == 0) red[tid >> 5] = lsum;
    __syncthreads();
    if (tid == 0) {
        float s0 = 0.f;
        for (int w = 0; w < NT / 32; w++) s0 += red[w];
        red[32] = s0;
    }
    __syncthreads();
    float inv = 1.f / red[32];

    cnt = 0;
    for (int j = tid; j <= i; j += NT) {
        float v = vals[cnt] * inv;
        cnt++;
        bf16 vh = f2bf(v);
        ahr[j] = vh;
        alr[j] = f2bf(v - bf2f(vh));
    }
    int jend = (((i >> 7) + 1) << 7);
    for (int j = i + 1 + tid; j < jend; j += NT) {
        ahr[j] = 0;
        alr[j] = 0;
    }
}

extern "C" void kernel_launch(void* const* d_in, const int* in_sizes, int n_in,
                              void* d_out, int out_size)
{
    const float* x     = (const float*)d_in[0];
    const float* w_qkv = (const float*)d_in[1];
    const float* w_out = (const float*)d_in[2];
    float* out = (float*)d_out;

    bf16 *xh, *xl, *wqh, *wql, *woh, *wol, *qh, *ql, *vth, *vtl;
    bf16 *t1h, *t1l, *sgh, *sgl, *ah, *al, *oh, *ol;
    float *sc, *su;
    cudaGetSymbolAddress((void**)&xh, g_xh);
    cudaGetSymbolAddress((void**)&xl, g_xl);
    cudaGetSymbolAddress((void**)&wqh, g_wqh);
    cudaGetSymbolAddress((void**)&wql, g_wql);
    cudaGetSymbolAddress((void**)&woh, g_woh);
    cudaGetSymbolAddress((void**)&wol, g_wol);
    cudaGetSymbolAddress((void**)&qh, g_qh);
    cudaGetSymbolAddress((void**)&ql, g_ql);
    cudaGetSymbolAddress((void**)&vth, g_vth);
    cudaGetSymbolAddress((void**)&vtl, g_vtl);
    cudaGetSymbolAddress((void**)&t1h, g_t1h);
    cudaGetSymbolAddress((void**)&t1l, g_t1l);
    cudaGetSymbolAddress((void**)&sgh, g_sgh);
    cudaGetSymbolAddress((void**)&sgl, g_sgl);
    cudaGetSymbolAddress((void**)&sc, g_sc);
    cudaGetSymbolAddress((void**)&su, g_su);
    cudaGetSymbolAddress((void**)&ah, g_ah);
    cudaGetSymbolAddress((void**)&al, g_al);
    cudaGetSymbolAddress((void**)&oh, g_oh);
    cudaGetSymbolAddress((void**)&ol, g_ol);

    const int SMT128 = 3 * (16384 + 128 * 128);  // 98304
    const int SMT64  = 3 * (16384 + 64 * 128);   // 73728
    cudaFuncSetAttribute(mma_gemm<128, 2>, cudaFuncAttributeMaxDynamicSharedMemorySize, SMT128);
    cudaFuncSetAttribute(mma_gemm<64, 4>, cudaFuncAttributeMaxDynamicSharedMemorySize, SMT64);

    // splits
    {
        int n4 = NSEQ * DIM / 4;
        split_kernel<<<(n4 + 255) / 256, 256>>>(x, xh, xl, n4);
        n4 = QKV6 * DIM / 4;
        split_kernel<<<(n4 + 255) / 256, 256>>>(w_qkv, wqh, wql, n4);
        n4 = DIM * DIM / 4;
        split_kernel<<<(n4 + 255) / 256, 256>>>(w_out, woh, wol, n4);
    }

    // 1) qkvs = x @ w_qkv^T (scale qu,qc by 0.125), split pair
    mma_gemm<128, 2><<<dim3(QKV6 / 128, NSEQ / 128, 1), 256, SMT128>>>(
        xh, xl, DIM, 0, wqh, wql, DIM, 0,
        (float*)0, qh, ql, QKV6, 0,
        DIM, 1, 0, 0);

    // 1b) transpose vc -> [64][N] per head
    transpose_vc<<<dim3(DIM / 32, NSEQ / 32), dim3(32, 8)>>>(qh, ql, vth, vtl);

    // component offsets: qu=0, ku=1024, vu=2048, qc=3072, kc=4096, vc=5120
    // 2) term1 = qc @ vu^T, lower incl diag
    mma_gemm<128, 2><<<dim3(16, 16, HEADS), 256, SMT128>>>(
        qh + 3072, ql + 3072, QKV6, 64, qh + 2048, ql + 2048, QKV6, 64,
        (float*)0, t1h, t1l, NSEQ, HSLL,
        64, 2, 1, 0);

    // 3) sig = sigmoid(qu @ ku^T), strict upper
    mma_gemm<128, 2><<<dim3(16, 16, HEADS), 256, SMT128>>>(
        qh + 0, ql + 0, QKV6, 64, qh + 1024, ql + 1024, QKV6, 64,
        (float*)0, sgh, sgl, NSEQ, HSLL,
        64, 3, 2, 0);

    // 4) Sc = qc @ kc^T (lower tiles only), fp32
    mma_gemm<128, 2><<<dim3(16, 16, HEADS), 256, SMT128>>>(
        qh + 3072, ql + 3072, QKV6, 64, qh + 4096, ql + 4096, QKV6, 64,
        sc, (bf16*)0, (bf16*)0, NSEQ, HSLL,
        64, 0, 1, 0);

    // 5) Su = term1 @ sig^T, triangular k-range, fp32
    mma_gemm<128, 2><<<dim3(16, 16, HEADS), 256, SMT128>>>(
        t1h, t1l, NSEQ, HSLL, sgh, sgl, NSEQ, HSLL,
        su, (bf16*)0, (bf16*)0, NSEQ, HSLL,
        NSEQ, 0, 1, 1);

    // 6) softmax -> attn split pair
    softmax_kernel<<<dim3(NSEQ, HEADS), 256>>>(sc, su, ah, al, NSEQ);

    // 7) o[:, h*64:(h+1)*64] = attn_h @ vcT_h (causal k-range)
    mma_gemm<64, 4><<<dim3(1, 16, HEADS), 256, SMT64>>>(
        ah, al, NSEQ, HSLL, vth, vtl, NSEQ, 64LL * NSEQ,
        (float*)0, oh, ol, HEADS * 64, 64,
        NSEQ, 4, 0, 2);

    // 8) out = o @ w_out^T, fp32
    mma_gemm<128, 2><<<dim3(DIM / 128, NSEQ / 128, 1), 256, SMT128>>>(
        oh, ol, HEADS * 64, 0, woh, wol, HEADS * 64, 0,
        out, (bf16*)0, (bf16*)0, DIM, 0,
        HEADS * 64, 0, 0, 0);
}

// round 9
// speedup vs baseline: 1.0574x; 1.0574x over previous
#include <cuda_runtime.h>
#include <math.h>
#include <stdint.h>

#define NSEQ 2048
#define DIM  1024
#define HEADS 16
#define QKV6 6144
#define HSLL ((long long)NSEQ * NSEQ)

typedef unsigned short bf16;

// ---------------- device scratch (allocation-free) ----------------
__device__ bf16 g_xh[NSEQ * DIM];
__device__ bf16 g_xl[NSEQ * DIM];
__device__ bf16 g_wqh[QKV6 * DIM];
__device__ bf16 g_wql[QKV6 * DIM];
__device__ bf16 g_woh[DIM * DIM];
__device__ bf16 g_wol[DIM * DIM];
__device__ bf16 g_qh[NSEQ * QKV6];
__device__ bf16 g_ql[NSEQ * QKV6];
__device__ bf16 g_vth[DIM * NSEQ];   // vc transposed: [h*64+d][n]
__device__ bf16 g_vtl[DIM * NSEQ];
__device__ bf16 g_t1h[(size_t)HEADS * NSEQ * NSEQ];
__device__ bf16 g_t1l[(size_t)HEADS * NSEQ * NSEQ];
__device__ bf16 g_sgh[(size_t)HEADS * NSEQ * NSEQ];
__device__ bf16 g_sgl[(size_t)HEADS * NSEQ * NSEQ];
__device__ float g_sc[(size_t)HEADS * NSEQ * NSEQ];
__device__ float g_su[(size_t)HEADS * NSEQ * NSEQ];
__device__ bf16 g_ah[(size_t)HEADS * NSEQ * NSEQ];
__device__ bf16 g_al[(size_t)HEADS * NSEQ * NSEQ];
__device__ bf16 g_oh[NSEQ * DIM];
__device__ bf16 g_ol[NSEQ * DIM];

// ---------------- helpers ----------------
__device__ __forceinline__ bf16 f2bf(float f) {
    bf16 h;
    asm("cvt.rn.bf16.f32 %0, %1;" : "=h"(h) : "f"(f));
    return h;
}
__device__ __forceinline__ float bf2f(bf16 h) {
    return __uint_as_float(((unsigned int)h) << 16);
}

__device__ __forceinline__ uint32_t smem_u32(const void* p) {
    uint32_t a;
    asm("{ .reg .u64 t; cvta.to.shared.u64 t, %1; cvt.u32.u64 %0, t; }" : "=r"(a) : "l"(p));
    return a;
}

__device__ __forceinline__ void cpa16(uint32_t saddr, const void* g) {
    asm volatile("cp.async.ca.shared.global [%0], [%1], 16;" :: "r"(saddr), "l"(g));
}
#define CP_COMMIT() asm volatile("cp.async.commit_group;" ::: "memory")
#define CP_WAIT0() asm volatile("cp.async.wait_group 0;" ::: "memory")
#define CP_WAIT1() asm volatile("cp.async.wait_group 1;" ::: "memory")

__device__ __forceinline__ void ldmA(uint32_t* r, uint32_t addr) {
    asm volatile("ldmatrix.sync.aligned.m8n8.x4.shared.b16 {%0,%1,%2,%3}, [%4];"
        : "=r"(r[0]), "=r"(r[1]), "=r"(r[2]), "=r"(r[3]) : "r"(addr));
}
__device__ __forceinline__ void ldmB(uint32_t* r, uint32_t addr) {
    asm volatile("ldmatrix.sync.aligned.m8n8.x2.shared.b16 {%0,%1}, [%2];"
        : "=r"(r[0]), "=r"(r[1]) : "r"(addr));
}

__device__ __forceinline__ void mma16816(float* d, const uint32_t* a, const uint32_t* b) {
    asm volatile(
        "mma.sync.aligned.m16n8k16.row.col.f32.bf16.bf16.f32 "
        "{%0,%1,%2,%3}, {%4,%5,%6,%7}, {%8,%9}, {%0,%1,%2,%3};"
        : "+f"(d[0]), "+f"(d[1]), "+f"(d[2]), "+f"(d[3])
        : "r"(a[0]), "r"(a[1]), "r"(a[2]), "r"(a[3]), "r"(b[0]), "r"(b[1]));
}

// SW128 swizzle for 128-byte rows: XOR bits[6:4] with row bits[2:0]
__device__ __forceinline__ uint32_t sw128(uint32_t off) {
    return off ^ ((off >> 3) & 0x70);
}

// ---------------- warp-MMA GEMM engine ----------------
// bf16x3 split; rows are 128B: [32 bf16 hi | 32 bf16 lo]; SW128 conflict-free ldmatrix.
// cp.async 2-stage (R7 ordering), BK=32.
// C[i0+m][n0+n] = sum_k A[m][k]*B[n][k]
// epi: 0 fp32; 1 qkv-scale + split; 2 mask j<=i + split; 3 sigmoid strict-upper + split; 4 split.
// skipm: 1 skip n0>i0; 2 skip n0<i0. trik: 1 -> k in [n0, i0+128); 2 -> k in [0, i0+128).
template<int BN, int WMC>
__global__ void __launch_bounds__(256, 2) mma_gemm(
    const bf16* __restrict__ Ah, const bf16* __restrict__ Al, int lda, long long sA,
    const bf16* __restrict__ Bh, const bf16* __restrict__ Bl, int ldb, long long sB,
    float* Cf, bf16* Ch, bf16* Cl, int ldc, long long sC,
    int K, int epi, int skipm, int trik)
{
    constexpr int WNC = 8 / WMC;
    constexpr int WM = 128 / WMC;
    constexpr int WN = BN / WNC;
    constexpr int MF = WM / 16;
    constexpr int NF = WN / 8;
    // stage layout: A 128 rows x 128B = 16KB, B BN rows x 128B
    constexpr int S_A = 0;
    constexpr int S_B = 16384;
    constexpr int STG = 16384 + BN * 128;

    int i0 = blockIdx.y * 128;
    int n0 = blockIdx.x * BN;
    if (skipm == 1 && n0 > i0) return;
    if (skipm == 2 && n0 < i0) return;
    int z = blockIdx.z;
    Ah += (long long)z * sA;
    Al += (long long)z * sA;
    Bh += (long long)z * sB;
    Bl += (long long)z * sB;
    if (Cf) Cf += (long long)z * sC;
    if (Ch) {
        Ch += (long long)z * sC;
        Cl += (long long)z * sC;
    }

    int kbeg = 0;
    int kend = K;
    if (trik == 1) {
        kbeg = n0;
        kend = i0 + 128;
        if (kend > K) kend = K;
    } else if (trik == 2) {
        kend = i0 + 128;
        if (kend > K) kend = K;
    }
    int nch = (kend - kbeg + 31) >> 5;

    extern __shared__ __align__(1024) char smem[];
    uint32_t sb = smem_u32(smem);
    int tid = threadIdx.x;
    int wid = tid >> 5;
    int lane = tid & 31;
    int wm = wid % WMC;
    int wn = wid / WMC;

    auto stage_chunk = [&](int buf, int kt) {
        uint32_t base = sb + buf * STG;
        for (int u = tid; u < 512; u += 256) {
            int r = u >> 2;
            int kb = u & 3;
            long long go = (long long)(i0 + r) * lda + kt + kb * 8;
            uint32_t off = ((uint32_t)r << 7) | ((uint32_t)kb << 4);
            cpa16(base + S_A + sw128(off), Ah + go);
            cpa16(base + S_A + sw128(off + 64), Al + go);
        }
        for (int u = tid; u < BN * 4; u += 256) {
            int r = u >> 2;
            int kb = u & 3;
            long long go = (long long)(n0 + r) * ldb + kt + kb * 8;
            uint32_t off = ((uint32_t)r << 7) | ((uint32_t)kb << 4);
            cpa16(base + S_B + sw128(off), Bh + go);
            cpa16(base + S_B + sw128(off + 64), Bl + go);
        }
    };

    float acc[MF][NF][4];
    #pragma unroll
    for (int a = 0; a < MF; a++)
        #pragma unroll
        for (int b = 0; b < NF; b++)
            #pragma unroll
            for (int c = 0; c < 4; c++)
                acc[a][b][c] = 0.f;

    stage_chunk(0, kbeg);
    CP_COMMIT();

    for (int t = 0; t < nch; t++) {
        if (t + 1 < nch) {
            stage_chunk((t + 1) & 1, kbeg + (t + 1) * 32);
            CP_COMMIT();
            CP_WAIT1();
        } else {
            CP_WAIT0();
        }
        __syncthreads();

        uint32_t cbase = sb + (t & 1) * STG;
        #pragma unroll
        for (int ks = 0; ks < 2; ks++) {
            int g = lane >> 3;
            int rowin = lane & 7;
            int kbA = ks * 32 + (g >> 1) * 16;
            uint32_t ahf[MF][4], alf[MF][4];
            #pragma unroll
            for (int mf = 0; mf < MF; mf++) {
                int r = wm * WM + mf * 16 + (g & 1) * 8 + rowin;
                uint32_t off = ((uint32_t)r << 7) + (uint32_t)kbA;
                ldmA(ahf[mf], cbase + S_A + sw128(off));
                ldmA(alf[mf], cbase + S_A + sw128(off + 64));
            }
            int kbB = ks * 32 + ((lane >> 3) & 1) * 16;
            uint32_t bhf[NF][2], blf[NF][2];
            #pragma unroll
            for (int nf = 0; nf < NF; nf++) {
                int r = wn * WN + nf * 8 + rowin;
                uint32_t off = ((uint32_t)r << 7) + (uint32_t)kbB;
                ldmB(bhf[nf], cbase + S_B + sw128(off));
                ldmB(blf[nf], cbase + S_B + sw128(off + 64));
            }
            #pragma unroll
            for (int mf = 0; mf < MF; mf++) {
                #pragma unroll
                for (int nf = 0; nf < NF; nf++) {
                    mma16816(acc[mf][nf], ahf[mf], bhf[nf]);
                    mma16816(acc[mf][nf], ahf[mf], blf[nf]);
                    mma16816(acc[mf][nf], alf[mf], bhf[nf]);
                }
            }
        }
        __syncthreads();
    }

    // epilogue from register fragments (vectorized 2-column stores)
    int crow = lane >> 2;
    int ccol = (lane & 3) * 2;
    #pragma unroll
    for (int mf = 0; mf < MF; mf++) {
        #pragma unroll
        for (int nf = 0; nf < NF; nf++) {
            #pragma unroll
            for (int c2 = 0; c2 < 2; c2++) {
                int gi = i0 + wm * WM + mf * 16 + crow + c2 * 8;
                int gj = n0 + wn * WN + nf * 8 + ccol;
                float v0 = acc[mf][nf][c2 * 2];
                float v1 = acc[mf][nf][c2 * 2 + 1];
                long long idx = (long long)gi * ldc + gj;
                if (epi == 0) {
                    float2 f2;
                    f2.x = v0;
                    f2.y = v1;
                    *(float2*)(Cf + idx) = f2;
                } else {
                    if (epi == 1) {
                        int c0 = gj >> 10;
                        int c1 = (gj + 1) >> 10;
                        if (c0 == 0 || c0 == 3) v0 *= 0.125f;
                        if (c1 == 0 || c1 == 3) v1 *= 0.125f;
                    } else if (epi == 2) {
                        v0 = (gj <= gi) ? v0 : 0.f;
                        v1 = (gj + 1 <= gi) ? v1 : 0.f;
                    } else if (epi == 3) {
                        v0 = (gj > gi) ? (1.f / (1.f + expf(-v0))) : 0.f;
                        v1 = (gj + 1 > gi) ? (1.f / (1.f + expf(-v1))) : 0.f;
                    }
                    bf16 h0 = f2bf(v0);
                    bf16 h1 = f2bf(v1);
                    uint32_t hp = (uint32_t)h0 | ((uint32_t)h1 << 16);
                    uint32_t lp = (uint32_t)f2bf(v0 - bf2f(h0)) | ((uint32_t)f2bf(v1 - bf2f(h1)) << 16);
                    *(uint32_t*)(Ch + idx) = hp;
                    *(uint32_t*)(Cl + idx) = lp;
                }
            }
        }
    }
}

// ---------------- split fp32 -> (hi, lo) bf16 ----------------
__global__ void split_kernel(const float* __restrict__ s, bf16* __restrict__ h,
                             bf16* __restrict__ l, int n4)
{
    int i = blockIdx.x * 256 + threadIdx.x;
    if (i < n4) {
        float4 v = ((const float4*)s)[i];
        float vv[4];
        vv[0] = v.x; vv[1] = v.y; vv[2] = v.z; vv[3] = v.w;
        for (int k = 0; k < 4; k++) {
            bf16 hh = f2bf(vv[k]);
            h[i * 4 + k] = hh;
            l[i * 4 + k] = f2bf(vv[k] - bf2f(hh));
        }
    }
}

// ---------------- transpose vc: [n][5120 + c] -> [c][n] ----------------
__global__ void transpose_vc(const bf16* __restrict__ qh, const bf16* __restrict__ ql,
                             bf16* __restrict__ vth, bf16* __restrict__ vtl)
{
    __shared__ bf16 th[32][33];
    __shared__ bf16 tl[32][33];
    int c0 = blockIdx.x * 32;
    int n0 = blockIdx.y * 32;
    int tx = threadIdx.x;
    int ty = threadIdx.y;
    for (int r = ty; r < 32; r += 8) {
        th[r][tx] = qh[(long long)(n0 + r) * QKV6 + 5120 + c0 + tx];
        tl[r][tx] = ql[(long long)(n0 + r) * QKV6 + 5120 + c0 + tx];
    }
    __syncthreads();
    for (int r = ty; r < 32; r += 8) {
        vth[(long long)(c0 + r) * NSEQ + n0 + tx] = th[tx][r];
        vtl[(long long)(c0 + r) * NSEQ + n0 + tx] = tl[tx][r];
    }
}

// ---------------- softmax(Sc - silu(Su)) over j<=i -> attn bf16 pair ----------------
__global__ void softmax_kernel(const float* __restrict__ sc, const float* __restrict__ su,
                               bf16* __restrict__ ah, bf16* __restrict__ al, int n)
{
    int i = blockIdx.x;
    int hh = blockIdx.y;
    long long base = ((long long)hh * n + i) * (long long)n;
    const float* scr = sc + base;
    const float* sur = su + base;
    bf16* ahr = ah + base;
    bf16* alr = al + base;

    int tid = threadIdx.x;
    const int NT = 256;
    float vals[8];
    int cnt = 0;
    float lmax = -INFINITY;
    for (int j = tid; j <= i; j += NT) {
        float u = sur[j];
        float sg = 1.f / (1.f + expf(-u));
        float s = scr[j] - u * sg;
        vals[cnt] = s;
        cnt++;
        lmax = fmaxf(lmax, s);
    }

    __shared__ float red[33];
    for (int o = 16; o > 0; o >>= 1) lmax = fmaxf(lmax, __shfl_xor_sync(0xffffffffu, lmax, o));
    if ((tid & 31) == 0) red[tid >> 5] = lmax;
    __syncthreads();
    if (tid == 0) {
        float m0 = red[0];
        for (int w = 1; w < NT / 32; w++) m0 = fmaxf(m0, red[w]);
        red[32] = m0;
    }
    __syncthreads();
    float m = red[32];
    __syncthreads();

    float lsum = 0.f;
    for (int c = 0; c < cnt; c++) {
        float e = expf(vals[c] - m);
        vals[c] = e;
        lsum += e;
    }
    for (int o = 16; o > 0; o >>= 1) lsum += __shfl_xor_sync(0xffffffffu, lsum, o);
    if ((tid & 31) == 0) red[tid >> 5] = lsum;
    __syncthreads();
    if (tid == 0) {
        float s0 = 0.f;
        for (int w = 0; w < NT / 32; w++) s0 += red[w];
        red[32] = s0;
    }
    __syncthreads();
    float inv = 1.f / red[32];

    cnt = 0;
    for (int j = tid; j <= i; j += NT) {
        float v = vals[cnt] * inv;
        cnt++;
        bf16 vh = f2bf(v);
        ahr[j] = vh;
        alr[j] = f2bf(v - bf2f(vh));
    }
    int jend = (((i >> 7) + 1) << 7);
    for (int j = i + 1 + tid; j < jend; j += NT) {
        ahr[j] = 0;
        alr[j] = 0;
    }
}

extern "C" void kernel_launch(void* const* d_in, const int* in_sizes, int n_in,
                              void* d_out, int out_size)
{
    const float* x     = (const float*)d_in[0];
    const float* w_qkv = (const float*)d_in[1];
    const float* w_out = (const float*)d_in[2];
    float* out = (float*)d_out;

    bf16 *xh, *xl, *wqh, *wql, *woh, *wol, *qh, *ql, *vth, *vtl;
    bf16 *t1h, *t1l, *sgh, *sgl, *ah, *al, *oh, *ol;
    float *sc, *su;
    cudaGetSymbolAddress((void**)&xh, g_xh);
    cudaGetSymbolAddress((void**)&xl, g_xl);
    cudaGetSymbolAddress((void**)&wqh, g_wqh);
    cudaGetSymbolAddress((void**)&wql, g_wql);
    cudaGetSymbolAddress((void**)&woh, g_woh);
    cudaGetSymbolAddress((void**)&wol, g_wol);
    cudaGetSymbolAddress((void**)&qh, g_qh);
    cudaGetSymbolAddress((void**)&ql, g_ql);
    cudaGetSymbolAddress((void**)&vth, g_vth);
    cudaGetSymbolAddress((void**)&vtl, g_vtl);
    cudaGetSymbolAddress((void**)&t1h, g_t1h);
    cudaGetSymbolAddress((void**)&t1l, g_t1l);
    cudaGetSymbolAddress((void**)&sgh, g_sgh);
    cudaGetSymbolAddress((void**)&sgl, g_sgl);
    cudaGetSymbolAddress((void**)&sc, g_sc);
    cudaGetSymbolAddress((void**)&su, g_su);
    cudaGetSymbolAddress((void**)&ah, g_ah);
    cudaGetSymbolAddress((void**)&al, g_al);
    cudaGetSymbolAddress((void**)&oh, g_oh);
    cudaGetSymbolAddress((void**)&ol, g_ol);

    const int SMT128 = 2 * (16384 + 128 * 128);  // 65536
    const int SMT64  = 2 * (16384 + 64 * 128);   // 49152
    cudaFuncSetAttribute(mma_gemm<128, 2>, cudaFuncAttributeMaxDynamicSharedMemorySize, SMT128);
    cudaFuncSetAttribute(mma_gemm<64, 4>, cudaFuncAttributeMaxDynamicSharedMemorySize, SMT64);

    // splits
    {
        int n4 = NSEQ * DIM / 4;
        split_kernel<<<(n4 + 255) / 256, 256>>>(x, xh, xl, n4);
        n4 = QKV6 * DIM / 4;
        split_kernel<<<(n4 + 255) / 256, 256>>>(w_qkv, wqh, wql, n4);
        n4 = DIM * DIM / 4;
        split_kernel<<<(n4 + 255) / 256, 256>>>(w_out, woh, wol, n4);
    }

    // 1) qkvs = x @ w_qkv^T (scale qu,qc by 0.125), split pair
    mma_gemm<128, 2><<<dim3(QKV6 / 128, NSEQ / 128, 1), 256, SMT128>>>(
        xh, xl, DIM, 0, wqh, wql, DIM, 0,
        (float*)0, qh, ql, QKV6, 0,
        DIM, 1, 0, 0);

    // 1b) transpose vc -> [64][N] per head
    transpose_vc<<<dim3(DIM / 32, NSEQ / 32), dim3(32, 8)>>>(qh, ql, vth, vtl);

    // component offsets: qu=0, ku=1024, vu=2048, qc=3072, kc=4096, vc=5120
    // 2) term1 = qc @ vu^T, lower incl diag
    mma_gemm<128, 2><<<dim3(16, 16, HEADS), 256, SMT128>>>(
        qh + 3072, ql + 3072, QKV6, 64, qh + 2048, ql + 2048, QKV6, 64,
        (float*)0, t1h, t1l, NSEQ, HSLL,
        64, 2, 1, 0);

    // 3) sig = sigmoid(qu @ ku^T), strict upper
    mma_gemm<128, 2><<<dim3(16, 16, HEADS), 256, SMT128>>>(
        qh + 0, ql + 0, QKV6, 64, qh + 1024, ql + 1024, QKV6, 64,
        (float*)0, sgh, sgl, NSEQ, HSLL,
        64, 3, 2, 0);

    // 4) Sc = qc @ kc^T (lower tiles only), fp32
    mma_gemm<128, 2><<<dim3(16, 16, HEADS), 256, SMT128>>>(
        qh + 3072, ql + 3072, QKV6, 64, qh + 4096, ql + 4096, QKV6, 64,
        sc, (bf16*)0, (bf16*)0, NSEQ, HSLL,
        64, 0, 1, 0);

    // 5) Su = term1 @ sig^T, triangular k-range, fp32
    mma_gemm<128, 2><<<dim3(16, 16, HEADS), 256, SMT128>>>(
        t1h, t1l, NSEQ, HSLL, sgh, sgl, NSEQ, HSLL,
        su, (bf16*)0, (bf16*)0, NSEQ, HSLL,
        NSEQ, 0, 1, 1);

    // 6) softmax -> attn split pair
    softmax_kernel<<<dim3(NSEQ, HEADS), 256>>>(sc, su, ah, al, NSEQ);

    // 7) o[:, h*64:(h+1)*64] = attn_h @ vcT_h (causal k-range)
    mma_gemm<64, 4><<<dim3(1, 16, HEADS), 256, SMT64>>>(
        ah, al, NSEQ, HSLL, vth, vtl, NSEQ, 64LL * NSEQ,
        (float*)0, oh, ol, HEADS * 64, 64,
        NSEQ, 4, 0, 2);

    // 8) out = o @ w_out^T, fp32
    mma_gemm<128, 2><<<dim3(DIM / 128, NSEQ / 128, 1), 256, SMT128>>>(
        oh, ol, HEADS * 64, 0, woh, wol, HEADS * 64, 0,
        out, (bf16*)0, (bf16*)0, DIM, 0,
        HEADS * 64, 0, 0, 0);
}

// round 10
// speedup vs baseline: 1.0879x; 1.0288x over previous
#include <cuda_runtime.h>
#include <math.h>
#include <stdint.h>

#define NSEQ 2048
#define DIM  1024
#define HEADS 16
#define QKV6 6144
#define HSLL ((long long)NSEQ * NSEQ)

typedef unsigned short bf16;

// ---------------- device scratch (allocation-free) ----------------
__device__ bf16 g_xh[NSEQ * DIM];
__device__ bf16 g_xl[NSEQ * DIM];
__device__ bf16 g_wqh[QKV6 * DIM];
__device__ bf16 g_wql[QKV6 * DIM];
__device__ bf16 g_woh[DIM * DIM];
__device__ bf16 g_wol[DIM * DIM];
__device__ bf16 g_qh[NSEQ * QKV6];
__device__ bf16 g_ql[NSEQ * QKV6];
__device__ bf16 g_vth[DIM * NSEQ];   // vc transposed: [h*64+d][n]
__device__ bf16 g_vtl[DIM * NSEQ];
__device__ bf16 g_t1h[(size_t)HEADS * NSEQ * NSEQ];
__device__ bf16 g_t1l[(size_t)HEADS * NSEQ * NSEQ];
__device__ bf16 g_sgh[(size_t)HEADS * NSEQ * NSEQ];
__device__ bf16 g_sgl[(size_t)HEADS * NSEQ * NSEQ];
__device__ float g_sc[(size_t)HEADS * NSEQ * NSEQ];
__device__ float g_su[(size_t)HEADS * NSEQ * NSEQ];
__device__ bf16 g_ah[(size_t)HEADS * NSEQ * NSEQ];
__device__ bf16 g_al[(size_t)HEADS * NSEQ * NSEQ];
__device__ bf16 g_oh[NSEQ * DIM];
__device__ bf16 g_ol[NSEQ * DIM];

// ---------------- helpers ----------------
__device__ __forceinline__ bf16 f2bf(float f) {
    bf16 h;
    asm("cvt.rn.bf16.f32 %0, %1;" : "=h"(h) : "f"(f));
    return h;
}
__device__ __forceinline__ float bf2f(bf16 h) {
    return __uint_as_float(((unsigned int)h) << 16);
}

__device__ __forceinline__ uint32_t smem_u32(const void* p) {
    uint32_t a;
    asm("{ .reg .u64 t; cvta.to.shared.u64 t, %1; cvt.u32.u64 %0, t; }" : "=r"(a) : "l"(p));
    return a;
}

__device__ __forceinline__ void cpa16(uint32_t saddr, const void* g) {
    asm volatile("cp.async.ca.shared.global [%0], [%1], 16;" :: "r"(saddr), "l"(g));
}
#define CP_COMMIT() asm volatile("cp.async.commit_group;" ::: "memory")
#define CP_WAIT0() asm volatile("cp.async.wait_group 0;" ::: "memory")
#define CP_WAIT1() asm volatile("cp.async.wait_group 1;" ::: "memory")

__device__ __forceinline__ void ldm4(uint32_t* r, uint32_t addr) {
    asm volatile("ldmatrix.sync.aligned.m8n8.x4.shared.b16 {%0,%1,%2,%3}, [%4];"
        : "=r"(r[0]), "=r"(r[1]), "=r"(r[2]), "=r"(r[3]) : "r"(addr));
}

__device__ __forceinline__ void mma16816(float* d, const uint32_t* a, const uint32_t* b) {
    asm volatile(
        "mma.sync.aligned.m16n8k16.row.col.f32.bf16.bf16.f32 "
        "{%0,%1,%2,%3}, {%4,%5,%6,%7}, {%8,%9}, {%0,%1,%2,%3};"
        : "+f"(d[0]), "+f"(d[1]), "+f"(d[2]), "+f"(d[3])
        : "r"(a[0]), "r"(a[1]), "r"(a[2]), "r"(a[3]), "r"(b[0]), "r"(b[1]));
}

// SW128 swizzle for 128-byte rows: XOR bits[6:4] with row bits[2:0]
__device__ __forceinline__ uint32_t sw128(uint32_t off) {
    return off ^ ((off >> 3) & 0x70);
}

// ---------------- warp-MMA GEMM engine ----------------
// bf16x3 split; rows are 128B: [32 bf16 hi | 32 bf16 lo]; SW128.
// cp.async 2-stage (R7 ordering), BK=32. B fragments loaded pairwise via ldmatrix.x4.
// C[i0+m][n0+n] = sum_k A[m][k]*B[n][k]
// epi: 0 fp32; 1 qkv-scale + split; 2 mask j<=i + split; 3 sigmoid strict-upper + split; 4 split.
// skipm: 1 skip n0>i0; 2 skip n0<i0. trik: 1 -> k in [n0, i0+128); 2 -> k in [0, i0+128).
template<int BN, int WMC>
__global__ void __launch_bounds__(256, 2) mma_gemm(
    const bf16* __restrict__ Ah, const bf16* __restrict__ Al, int lda, long long sA,
    const bf16* __restrict__ Bh, const bf16* __restrict__ Bl, int ldb, long long sB,
    float* Cf, bf16* Ch, bf16* Cl, int ldc, long long sC,
    int K, int epi, int skipm, int trik)
{
    constexpr int WNC = 8 / WMC;
    constexpr int WM = 128 / WMC;
    constexpr int WN = BN / WNC;
    constexpr int MF = WM / 16;
    constexpr int NF = WN / 8;
    // stage layout: A 128 rows x 128B = 16KB, B BN rows x 128B
    constexpr int S_A = 0;
    constexpr int S_B = 16384;
    constexpr int STG = 16384 + BN * 128;

    int i0 = blockIdx.y * 128;
    int n0 = blockIdx.x * BN;
    if (skipm == 1 && n0 > i0) return;
    if (skipm == 2 && n0 < i0) return;
    int z = blockIdx.z;
    Ah += (long long)z * sA;
    Al += (long long)z * sA;
    Bh += (long long)z * sB;
    Bl += (long long)z * sB;
    if (Cf) Cf += (long long)z * sC;
    if (Ch) {
        Ch += (long long)z * sC;
        Cl += (long long)z * sC;
    }

    int kbeg = 0;
    int kend = K;
    if (trik == 1) {
        kbeg = n0;
        kend = i0 + 128;
        if (kend > K) kend = K;
    } else if (trik == 2) {
        kend = i0 + 128;
        if (kend > K) kend = K;
    }
    int nch = (kend - kbeg + 31) >> 5;

    extern __shared__ __align__(1024) char smem[];
    uint32_t sb = smem_u32(smem);
    int tid = threadIdx.x;
    int wid = tid >> 5;
    int lane = tid & 31;
    int wm = wid % WMC;
    int wn = wid / WMC;

    auto stage_chunk = [&](int buf, int kt) {
        uint32_t base = sb + buf * STG;
        for (int u = tid; u < 512; u += 256) {
            int r = u >> 2;
            int kb = u & 3;
            long long go = (long long)(i0 + r) * lda + kt + kb * 8;
            uint32_t off = ((uint32_t)r << 7) | ((uint32_t)kb << 4);
            cpa16(base + S_A + sw128(off), Ah + go);
            cpa16(base + S_A + sw128(off + 64), Al + go);
        }
        for (int u = tid; u < BN * 4; u += 256) {
            int r = u >> 2;
            int kb = u & 3;
            long long go = (long long)(n0 + r) * ldb + kt + kb * 8;
            uint32_t off = ((uint32_t)r << 7) | ((uint32_t)kb << 4);
            cpa16(base + S_B + sw128(off), Bh + go);
            cpa16(base + S_B + sw128(off + 64), Bl + go);
        }
    };

    float acc[MF][NF][4];
    #pragma unroll
    for (int a = 0; a < MF; a++)
        #pragma unroll
        for (int b = 0; b < NF; b++)
            #pragma unroll
            for (int c = 0; c < 4; c++)
                acc[a][b][c] = 0.f;

    stage_chunk(0, kbeg);
    CP_COMMIT();

    for (int t = 0; t < nch; t++) {
        if (t + 1 < nch) {
            stage_chunk((t + 1) & 1, kbeg + (t + 1) * 32);
            CP_COMMIT();
            CP_WAIT1();
        } else {
            CP_WAIT0();
        }
        __syncthreads();

        uint32_t cbase = sb + (t & 1) * STG;
        #pragma unroll
        for (int ks = 0; ks < 2; ks++) {
            int g = lane >> 3;
            int rowin = lane & 7;
            // A fragments: x4 per mf (16m x 16k), hi and lo
            int kbA = ks * 32 + (g >> 1) * 16;
            uint32_t ahf[MF][4], alf[MF][4];
            #pragma unroll
            for (int mf = 0; mf < MF; mf++) {
                int r = wm * WM + mf * 16 + (g & 1) * 8 + rowin;
                uint32_t off = ((uint32_t)r << 7) + (uint32_t)kbA;
                ldm4(ahf[mf], cbase + S_A + sw128(off));
                ldm4(alf[mf], cbase + S_A + sw128(off + 64));
            }
            // B fragments: x4 loads a PAIR of n8 tiles (nf, nf+1)
            // lanes 0-7: nf rows k0-7 | 8-15: nf rows k8-15 | 16-23: nf+1 rows k0-7 | 24-31: nf+1 rows k8-15
            int kbB = ks * 32 + ((lane >> 3) & 1) * 16;
            int rowB = ((lane >> 4) & 1) * 8 + rowin;
            uint32_t bhf[NF][2], blf[NF][2];
            #pragma unroll
            for (int nfp = 0; nfp < NF; nfp += 2) {
                int r = wn * WN + nfp * 8 + rowB;
                uint32_t off = ((uint32_t)r << 7) + (uint32_t)kbB;
                uint32_t q[4];
                ldm4(q, cbase + S_B + sw128(off));
                bhf[nfp][0] = q[0]; bhf[nfp][1] = q[1];
                bhf[nfp + 1][0] = q[2]; bhf[nfp + 1][1] = q[3];
                ldm4(q, cbase + S_B + sw128(off + 64));
                blf[nfp][0] = q[0]; blf[nfp][1] = q[1];
                blf[nfp + 1][0] = q[2]; blf[nfp + 1][1] = q[3];
            }
            #pragma unroll
            for (int mf = 0; mf < MF; mf++) {
                #pragma unroll
                for (int nf = 0; nf < NF; nf++) {
                    mma16816(acc[mf][nf], ahf[mf], bhf[nf]);
                    mma16816(acc[mf][nf], ahf[mf], blf[nf]);
                    mma16816(acc[mf][nf], alf[mf], bhf[nf]);
                }
            }
        }
        __syncthreads();
    }

    // epilogue from register fragments (vectorized 2-column stores)
    int crow = lane >> 2;
    int ccol = (lane & 3) * 2;
    #pragma unroll
    for (int mf = 0; mf < MF; mf++) {
        #pragma unroll
        for (int nf = 0; nf < NF; nf++) {
            #pragma unroll
            for (int c2 = 0; c2 < 2; c2++) {
                int gi = i0 + wm * WM + mf * 16 + crow + c2 * 8;
                int gj = n0 + wn * WN + nf * 8 + ccol;
                float v0 = acc[mf][nf][c2 * 2];
                float v1 = acc[mf][nf][c2 * 2 + 1];
                long long idx = (long long)gi * ldc + gj;
                if (epi == 0) {
                    float2 f2;
                    f2.x = v0;
                    f2.y = v1;
                    *(float2*)(Cf + idx) = f2;
                } else {
                    if (epi == 1) {
                        int c0 = gj >> 10;
                        int c1 = (gj + 1) >> 10;
                        if (c0 == 0 || c0 == 3) v0 *= 0.125f;
                        if (c1 == 0 || c1 == 3) v1 *= 0.125f;
                    } else if (epi == 2) {
                        v0 = (gj <= gi) ? v0 : 0.f;
                        v1 = (gj + 1 <= gi) ? v1 : 0.f;
                    } else if (epi == 3) {
                        v0 = (gj > gi) ? (1.f / (1.f + expf(-v0))) : 0.f;
                        v1 = (gj + 1 > gi) ? (1.f / (1.f + expf(-v1))) : 0.f;
                    }
                    bf16 h0 = f2bf(v0);
                    bf16 h1 = f2bf(v1);
                    uint32_t hp = (uint32_t)h0 | ((uint32_t)h1 << 16);
                    uint32_t lp = (uint32_t)f2bf(v0 - bf2f(h0)) | ((uint32_t)f2bf(v1 - bf2f(h1)) << 16);
                    *(uint32_t*)(Ch + idx) = hp;
                    *(uint32_t*)(Cl + idx) = lp;
                }
            }
        }
    }
}

// ---------------- split fp32 -> (hi, lo) bf16 ----------------
__global__ void split_kernel(const float* __restrict__ s, bf16* __restrict__ h,
                             bf16* __restrict__ l, int n4)
{
    int i = blockIdx.x * 256 + threadIdx.x;
    if (i < n4) {
        float4 v = ((const float4*)s)[i];
        float vv[4];
        vv[0] = v.x; vv[1] = v.y; vv[2] = v.z; vv[3] = v.w;
        for (int k = 0; k < 4; k++) {
            bf16 hh = f2bf(vv[k]);
            h[i * 4 + k] = hh;
            l[i * 4 + k] = f2bf(vv[k] - bf2f(hh));
        }
    }
}

// ---------------- transpose vc: [n][5120 + c] -> [c][n] ----------------
__global__ void transpose_vc(const bf16* __restrict__ qh, const bf16* __restrict__ ql,
                             bf16* __restrict__ vth, bf16* __restrict__ vtl)
{
    __shared__ bf16 th[32][33];
    __shared__ bf16 tl[32][33];
    int c0 = blockIdx.x * 32;
    int n0 = blockIdx.y * 32;
    int tx = threadIdx.x;
    int ty = threadIdx.y;
    for (int r = ty; r < 32; r += 8) {
        th[r][tx] = qh[(long long)(n0 + r) * QKV6 + 5120 + c0 + tx];
        tl[r][tx] = ql[(long long)(n0 + r) * QKV6 + 5120 + c0 + tx];
    }
    __syncthreads();
    for (int r = ty; r < 32; r += 8) {
        vth[(long long)(c0 + r) * NSEQ + n0 + tx] = th[tx][r];
        vtl[(long long)(c0 + r) * NSEQ + n0 + tx] = tl[tx][r];
    }
}

// ---------------- softmax(Sc - silu(Su)) over j<=i -> attn bf16 pair ----------------
__global__ void softmax_kernel(const float* __restrict__ sc, const float* __restrict__ su,
                               bf16* __restrict__ ah, bf16* __restrict__ al, int n)
{
    int i = blockIdx.x;
    int hh = blockIdx.y;
    long long base = ((long long)hh * n + i) * (long long)n;
    const float* scr = sc + base;
    const float* sur = su + base;
    bf16* ahr = ah + base;
    bf16* alr = al + base;

    int tid = threadIdx.x;
    const int NT = 256;
    float vals[8];
    int cnt = 0;
    float lmax = -INFINITY;
    for (int j = tid; j <= i; j += NT) {
        float u = sur[j];
        float sg = 1.f / (1.f + expf(-u));
        float s = scr[j] - u * sg;
        vals[cnt] = s;
        cnt++;
        lmax = fmaxf(lmax, s);
    }

    __shared__ float red[33];
    for (int o = 16; o > 0; o >>= 1) lmax = fmaxf(lmax, __shfl_xor_sync(0xffffffffu, lmax, o));
    if ((tid & 31) == 0) red[tid >> 5] = lmax;
    __syncthreads();
    if (tid == 0) {
        float m0 = red[0];
        for (int w = 1; w < NT / 32; w++) m0 = fmaxf(m0, red[w]);
        red[32] = m0;
    }
    __syncthreads();
    float m = red[32];
    __syncthreads();

    float lsum = 0.f;
    for (int c = 0; c < cnt; c++) {
        float e = expf(vals[c] - m);
        vals[c] = e;
        lsum += e;
    }
    for (int o = 16; o > 0; o >>= 1) lsum += __shfl_xor_sync(0xffffffffu, lsum, o);
    if ((tid & 31) == 0) red[tid >> 5] = lsum;
    __syncthreads();
    if (tid == 0) {
        float s0 = 0.f;
        for (int w = 0; w < NT / 32; w++) s0 += red[w];
        red[32] = s0;
    }
    __syncthreads();
    float inv = 1.f / red[32];

    cnt = 0;
    for (int j = tid; j <= i; j += NT) {
        float v = vals[cnt] * inv;
        cnt++;
        bf16 vh = f2bf(v);
        ahr[j] = vh;
        alr[j] = f2bf(v - bf2f(vh));
    }
    int jend = (((i >> 7) + 1) << 7);
    for (int j = i + 1 + tid; j < jend; j += NT) {
        ahr[j] = 0;
        alr[j] = 0;
    }
}

extern "C" void kernel_launch(void* const* d_in, const int* in_sizes, int n_in,
                              void* d_out, int out_size)
{
    const float* x     = (const float*)d_in[0];
    const float* w_qkv = (const float*)d_in[1];
    const float* w_out = (const float*)d_in[2];
    float* out = (float*)d_out;

    bf16 *xh, *xl, *wqh, *wql, *woh, *wol, *qh, *ql, *vth, *vtl;
    bf16 *t1h, *t1l, *sgh, *sgl, *ah, *al, *oh, *ol;
    float *sc, *su;
    cudaGetSymbolAddress((void**)&xh, g_xh);
    cudaGetSymbolAddress((void**)&xl, g_xl);
    cudaGetSymbolAddress((void**)&wqh, g_wqh);
    cudaGetSymbolAddress((void**)&wql, g_wql);
    cudaGetSymbolAddress((void**)&woh, g_woh);
    cudaGetSymbolAddress((void**)&wol, g_wol);
    cudaGetSymbolAddress((void**)&qh, g_qh);
    cudaGetSymbolAddress((void**)&ql, g_ql);
    cudaGetSymbolAddress((void**)&vth, g_vth);
    cudaGetSymbolAddress((void**)&vtl, g_vtl);
    cudaGetSymbolAddress((void**)&t1h, g_t1h);
    cudaGetSymbolAddress((void**)&t1l, g_t1l);
    cudaGetSymbolAddress((void**)&sgh, g_sgh);
    cudaGetSymbolAddress((void**)&sgl, g_sgl);
    cudaGetSymbolAddress((void**)&sc, g_sc);
    cudaGetSymbolAddress((void**)&su, g_su);
    cudaGetSymbolAddress((void**)&ah, g_ah);
    cudaGetSymbolAddress((void**)&al, g_al);
    cudaGetSymbolAddress((void**)&oh, g_oh);
    cudaGetSymbolAddress((void**)&ol, g_ol);

    const int SMT128 = 2 * (16384 + 128 * 128);  // 65536
    const int SMT64  = 2 * (16384 + 64 * 128);   // 49152
    cudaFuncSetAttribute(mma_gemm<128, 2>, cudaFuncAttributeMaxDynamicSharedMemorySize, SMT128);
    cudaFuncSetAttribute(mma_gemm<64, 4>, cudaFuncAttributeMaxDynamicSharedMemorySize, SMT64);

    // splits
    {
        int n4 = NSEQ * DIM / 4;
        split_kernel<<<(n4 + 255) / 256, 256>>>(x, xh, xl, n4);
        n4 = QKV6 * DIM / 4;
        split_kernel<<<(n4 + 255) / 256, 256>>>(w_qkv, wqh, wql, n4);
        n4 = DIM * DIM / 4;
        split_kernel<<<(n4 + 255) / 256, 256>>>(w_out, woh, wol, n4);
    }

    // 1) qkvs = x @ w_qkv^T (scale qu,qc by 0.125), split pair
    mma_gemm<128, 2><<<dim3(QKV6 / 128, NSEQ / 128, 1), 256, SMT128>>>(
        xh, xl, DIM, 0, wqh, wql, DIM, 0,
        (float*)0, qh, ql, QKV6, 0,
        DIM, 1, 0, 0);

    // 1b) transpose vc -> [64][N] per head
    transpose_vc<<<dim3(DIM / 32, NSEQ / 32), dim3(32, 8)>>>(qh, ql, vth, vtl);

    // component offsets: qu=0, ku=1024, vu=2048, qc=3072, kc=4096, vc=5120
    // 2) term1 = qc @ vu^T, lower incl diag
    mma_gemm<128, 2><<<dim3(16, 16, HEADS), 256, SMT128>>>(
        qh + 3072, ql + 3072, QKV6, 64, qh + 2048, ql + 2048, QKV6, 64,
        (float*)0, t1h, t1l, NSEQ, HSLL,
        64, 2, 1, 0);

    // 3) sig = sigmoid(qu @ ku^T), strict upper
    mma_gemm<128, 2><<<dim3(16, 16, HEADS), 256, SMT128>>>(
        qh + 0, ql + 0, QKV6, 64, qh + 1024, ql + 1024, QKV6, 64,
        (float*)0, sgh, sgl, NSEQ, HSLL,
        64, 3, 2, 0);

    // 4) Sc = qc @ kc^T (lower tiles only), fp32
    mma_gemm<128, 2><<<dim3(16, 16, HEADS), 256, SMT128>>>(
        qh + 3072, ql + 3072, QKV6, 64, qh + 4096, ql + 4096, QKV6, 64,
        sc, (bf16*)0, (bf16*)0, NSEQ, HSLL,
        64, 0, 1, 0);

    // 5) Su = term1 @ sig^T, triangular k-range, fp32
    mma_gemm<128, 2><<<dim3(16, 16, HEADS), 256, SMT128>>>(
        t1h, t1l, NSEQ, HSLL, sgh, sgl, NSEQ, HSLL,
        su, (bf16*)0, (bf16*)0, NSEQ, HSLL,
        NSEQ, 0, 1, 1);

    // 6) softmax -> attn split pair
    softmax_kernel<<<dim3(NSEQ, HEADS), 256>>>(sc, su, ah, al, NSEQ);

    // 7) o[:, h*64:(h+1)*64] = attn_h @ vcT_h (causal k-range)
    mma_gemm<64, 4><<<dim3(1, 16, HEADS), 256, SMT64>>>(
        ah, al, NSEQ, HSLL, vth, vtl, NSEQ, 64LL * NSEQ,
        (float*)0, oh, ol, HEADS * 64, 64,
        NSEQ, 4, 0, 2);

    // 8) out = o @ w_out^T, fp32
    mma_gemm<128, 2><<<dim3(DIM / 128, NSEQ / 128, 1), 256, SMT128>>>(
        oh, ol, HEADS * 64, 0, woh, wol, HEADS * 64, 0,
        out, (bf16*)0, (bf16*)0, DIM, 0,
        HEADS * 64, 0, 0, 0);
}